// round 5
// baseline (speedup 1.0000x reference)
#include <cuda_runtime.h>

#define BATCH 256
#define NROWS 256
#define MCOLS 256
#define DDIM  32
#define TPB   128                    // 4 warps, 2 DP rows per thread
#define NWARP 4
#define EXSKEW 16                    // inter-warp pipeline slack (steps)
#define OMAX  (TPB - 1 + EXSKEW * (NWARP - 1))   // 175
#define STEPS (MCOLS + OMAX)                     // 431
#define LOG2E 1.4426950408889634f
#define LN2   0.6931471805599453f
#define NEGE  (-(1 << 28))           // exponent of exact-zero values
#define EBIAS (1 << 28)              // ring exponent bias (sentinel = 0xFFFFFFFF)

__device__ float g_part[BATCH];
__device__ int   g_count;

typedef unsigned long long u64;

#define FMA_F32X2(d, a, b) \
    asm("fma.rn.f32x2 %0, %1, %2, %0;" : "+l"(d) : "l"(a), "l"(b))
#define PACK_F32X2(out, lo, hi) \
    asm("mov.b64 %0, {%1, %2};" : "=l"(out) : "f"(lo), "f"(hi))
#define UNPACK_F32X2(lo, hi, in) \
    asm("mov.b64 {%0, %1}, %2;" : "=f"(lo), "=f"(hi) : "l"(in))

__device__ __forceinline__ float ex2f(float x) {
    float r; asm("ex2.approx.f32 %0, %1;" : "=f"(r) : "f"(x)); return r;
}
__device__ __forceinline__ float lg2f(float x) {
    float r; asm("lg2.approx.f32 %0, %1;" : "=f"(r) : "f"(x)); return r;
}

// 2^delta for delta <= 0; delta <= -127 flushes to +0 (negligible-term case)
__device__ __forceinline__ float escale(int delta) {
    delta = max(delta, -127);
    return __int_as_float((delta + 127) << 23);
}

// One DP cell in block-floating-point exp domain.
// inputs: up (vu,eu), left (vl,el), diag (vd,ed); weight e^(-d) = wf * 2^(-di)
// output: normalized (vn in {0} U [1,2), en)
__device__ __forceinline__ void cell(float vu, int eu, float vl, int el,
                                     float vd, int ed, float wf, int di,
                                     float& vn, int& en) {
    int base = max(max(eu, el), ed);
    float su = escale(eu - base);
    float sl = escale(el - base);
    float sd = escale(ed - base);
    float sum = vu * su + vl * sl + vd * sd;
    float v = wf * sum;                       // in (0.5, 8.6) or exactly 0
    int bits = __float_as_int(v);
    int k = (bits >> 23) - 127;
    float m = __int_as_float((bits & 0x007fffff) | 0x3f800000);
    bool z = (v == 0.0f);
    vn = z ? 0.0f : m;
    en = z ? NEGE : (base - di + k);
}

__global__ __launch_bounds__(TPB)
void sdtw_kernel(const float* __restrict__ X, const float* __restrict__ Y,
                 float* __restrict__ out) {
    __shared__ ulonglong2 sy4[8 * 257];            // y chunk-transposed, padded
    __shared__ float      sy2[MCOLS];              // ||y_j||^2 (natural units)
    __shared__ u64        ring[NWARP - 1][MCOLS];  // (exp+bias | mantissa bits)
    __shared__ float      red[TPB];
    __shared__ int        islast;

    const int t    = threadIdx.x;
    const int lane = t & 31;
    const int w    = t >> 5;
    const int o    = t + EXSKEW * w;
    const int b    = blockIdx.x;
    const float* xb = X + (size_t)b * NROWS * DDIM;
    const float* yb = Y + (size_t)b * MCOLS * DDIM;

    // ---- stage y (chunk-transposed), coalesced 16B ----
    const ulonglong2* yb16 = (const ulonglong2*)yb;
    for (int k = t; k < MCOLS * 8; k += TPB) {
        int j = k >> 3, c = k & 7;
        sy4[c * 257 + j] = yb16[k];
    }
    for (int j = t; j < MCOLS; j += TPB) {
        const float4* row = (const float4*)(yb + j * DDIM);
        float acc = 0.f;
        #pragma unroll
        for (int c = 0; c < 8; c++) {
            float4 v = row[c];
            acc += v.x * v.x + v.y * v.y + v.z * v.z + v.w * v.w;
        }
        sy2[j] = acc;
    }
    // ---- ring sentinel init ----
    for (int k = t; k < (NWARP - 1) * MCOLS; k += TPB)
        ((u64*)ring)[k] = 0xFFFFFFFF00000000ull;

    // ---- x rows packed f32x2 ----
    u64 ax0[16], ax1[16];
    float xx0 = 0.f, xx1 = 0.f;
    {
        const float4* r0 = (const float4*)(xb + (size_t)(2 * t)     * DDIM);
        const float4* r1 = (const float4*)(xb + (size_t)(2 * t + 1) * DDIM);
        #pragma unroll
        for (int c = 0; c < 8; c++) {
            float4 v0 = r0[c], v1r = r1[c];
            PACK_F32X2(ax0[2*c],   v0.x,  v0.y);
            PACK_F32X2(ax0[2*c+1], v0.z,  v0.w);
            PACK_F32X2(ax1[2*c],   v1r.x, v1r.y);
            PACK_F32X2(ax1[2*c+1], v1r.z, v1r.w);
            xx0 += v0.x*v0.x + v0.y*v0.y + v0.z*v0.z + v0.w*v0.w;
            xx1 += v1r.x*v1r.x + v1r.y*v1r.y + v1r.z*v1r.z + v1r.w*v1r.w;
        }
    }
    __syncthreads();

    // ---- DP state: E = e^(-D) as (mantissa, exponent) per row ----
    float lv0 = 0.f, lv1 = 0.f, tv = (t == 0) ? 1.f : 0.f;
    int   le0 = NEGE, le1 = NEGE, te = (t == 0) ? 0 : NEGE;
    float v1 = 0.f; int e1 = NEGE;      // bottom-row value for handoff

    volatile u64* myring = (w < NWARP - 1) ? &ring[w][0]     : 0;
    volatile u64* upring = (w > 0)         ? &ring[w - 1][0] : 0;

    #pragma unroll 1
    for (int s = 0; s < STEPS; s++) {
        float upv_sh = __shfl_up_sync(0xffffffffu, v1, 1);
        int   upe_sh = __shfl_up_sync(0xffffffffu, e1, 1);
        const int jj = s - o;
        if (jj >= 0 && jj < MCOLS) {
            // ---- distances (independent of DP chain) ----
            u64 a0 = 0ull, b0 = 0ull, a1 = 0ull, b1 = 0ull;
            #pragma unroll
            for (int c = 0; c < 8; c++) {
                ulonglong2 yv = sy4[c * 257 + jj];   // LDS.128 -> two f32x2
                FMA_F32X2(a0, ax0[2*c],   yv.x);
                FMA_F32X2(b0, ax0[2*c+1], yv.y);
                FMA_F32X2(a1, ax1[2*c],   yv.x);
                FMA_F32X2(b1, ax1[2*c+1], yv.y);
            }
            float l0,h0,l0b,h0b,l1,h1,l1b,h1b;
            UNPACK_F32X2(l0,  h0,  a0);
            UNPACK_F32X2(l0b, h0b, b0);
            UNPACK_F32X2(l1,  h1,  a1);
            UNPACK_F32X2(l1b, h1b, b1);
            float dot0 = (l0 + h0) + (l0b + h0b);
            float dot1 = (l1 + h1) + (l1b + h1b);
            float yy = sy2[jj];
            float dist0 = fmaxf(fmaf(-2.f, dot0, xx0 + yy), 0.f);
            float dist1 = fmaxf(fmaf(-2.f, dot1, xx1 + yy), 0.f);
            // weight e^(-d) = wf * 2^(-di), wf in [0.707, 1.415]
            float dl0 = dist0 * LOG2E, dl1 = dist1 * LOG2E;
            float df0 = rintf(dl0),    df1 = rintf(dl1);
            float wf0 = ex2f(df0 - dl0), wf1 = ex2f(df1 - dl1);
            int   di0 = (int)df0,      di1 = (int)df1;

            // ---- up value ----
            float uv; int ue;
            if (lane == 0) {
                if (w == 0) { uv = 0.f; ue = NEGE; }
                else {
                    u64 word = upring[jj];
                    while ((unsigned)(word >> 32) == 0xFFFFFFFFu)
                        word = upring[jj];
                    uv = __uint_as_float((unsigned)word);
                    ue = (int)(unsigned)(word >> 32) - EBIAS;
                }
            } else { uv = upv_sh; ue = upe_sh; }

            // ---- 2 cells, short linear chains ----
            float v0; int e0;
            cell(uv, ue, lv0, le0, tv, te, wf0, di0, v0, e0);
            float nv1; int ne1;
            cell(v0, e0, lv1, le1, lv0, le0, wf1, di1, nv1, ne1);
            tv = uv; te = ue;
            lv0 = v0; le0 = e0;
            lv1 = nv1; le1 = ne1;
            v1 = nv1; e1 = ne1;

            if (lane == 31 && w < NWARP - 1)
                myring[jj] = ((u64)(unsigned)(ne1 + EBIAS) << 32)
                           | (u64)__float_as_uint(nv1);

            if (t == TPB - 1 && jj == MCOLS - 1) {
                // D = -ln(E) = -(log2(m) + e) * ln2
                float l2 = lg2f(nv1) + (float)ne1;
                g_part[b] = -l2 * LN2;
            }
        }
    }

    // ---- fused grid reduction (last CTA) ----
    __threadfence();
    __syncthreads();
    if (t == 0) islast = (atomicAdd(&g_count, 1) == BATCH - 1);
    __syncthreads();
    if (islast) {
        __threadfence();
        red[t] = g_part[t] + g_part[t + TPB];
        __syncthreads();
        #pragma unroll
        for (int off = TPB / 2; off > 0; off >>= 1) {
            if (t < off) red[t] += red[t + off];
            __syncthreads();
        }
        if (t == 0) {
            out[0] = red[0] * (1.0f / (float)BATCH);
            g_count = 0;                 // reset for next graph replay
        }
    }
}

extern "C" void kernel_launch(void* const* d_in, const int* in_sizes, int n_in,
                              void* d_out, int out_size) {
    const float* x = (const float*)d_in[0];
    const float* y = (const float*)d_in[1];
    float* out = (float*)d_out;
    sdtw_kernel<<<BATCH, TPB>>>(x, y, out);
}

// round 6
// speedup vs baseline: 2.4561x; 2.4561x over previous
#include <cuda_runtime.h>

#define BATCH 256
#define NROWS 256
#define MCOLS 256
#define DDIM  32
#define TPB   128                    // 4 warps, 2 DP rows per thread
#define NWARP 4
#define SLACK 8                      // startup ring cushion (columns)
#define ITERS (MCOLS + 31)           // 287 warp-local iterations
#define LOG2E 1.4426950408889634f
#define BIGF  (1e8f * LOG2E)         // boundary in scaled (D*log2e) domain

__device__ float g_part[BATCH];
__device__ int   g_count;

typedef unsigned long long u64;

#define FMA_F32X2(d, a, b) \
    asm("fma.rn.f32x2 %0, %1, %2, %0;" : "+l"(d) : "l"(a), "l"(b))
#define PACK_F32X2(out, lo, hi) \
    asm("mov.b64 %0, {%1, %2};" : "=l"(out) : "f"(lo), "f"(hi))
#define UNPACK_F32X2(lo, hi, in) \
    asm("mov.b64 {%0, %1}, %2;" : "=f"(lo), "=f"(hi) : "l"(in))

__device__ __forceinline__ float ex2f(float x) {
    float r; asm("ex2.approx.f32 %0, %1;" : "=f"(r) : "f"(x)); return r;
}
__device__ __forceinline__ float lg2f(float x) {
    float r; asm("lg2.approx.f32 %0, %1;" : "=f"(r) : "f"(x)); return r;
}

// softmin in scaled (D*log2e) domain
__device__ __forceinline__ float softmin3s(float a, float b, float c) {
    float mn = fminf(fminf(a, b), c);
    float s  = ex2f(mn - a) + ex2f(mn - b) + ex2f(mn - c);
    return mn - lg2f(s);
}

__global__ __launch_bounds__(TPB)
void sdtw_kernel(const float* __restrict__ X, const float* __restrict__ Y,
                 float* __restrict__ out) {
    __shared__ ulonglong2 sy4[8 * 257];            // y chunk-transposed, padded
    __shared__ float      sy2[MCOLS];              // ||y_j||^2 * log2e
    __shared__ u64        ring[NWARP - 1][MCOLS];  // tagged (col+1 | value bits)
    __shared__ float      red[TPB];
    __shared__ int        islast;

    const int t    = threadIdx.x;
    const int lane = t & 31;
    const int w    = t >> 5;
    const int b    = blockIdx.x;
    const float* xb = X + (size_t)b * NROWS * DDIM;
    const float* yb = Y + (size_t)b * MCOLS * DDIM;

    // ---- stage y (chunk-transposed), coalesced 16B ----
    const ulonglong2* yb16 = (const ulonglong2*)yb;
    for (int k = t; k < MCOLS * 8; k += TPB) {
        int j = k >> 3, c = k & 7;
        sy4[c * 257 + j] = yb16[k];
    }
    for (int j = t; j < MCOLS; j += TPB) {
        const float4* row = (const float4*)(yb + j * DDIM);
        float acc = 0.f;
        #pragma unroll
        for (int c = 0; c < 8; c++) {
            float4 v = row[c];
            acc += v.x * v.x + v.y * v.y + v.z * v.z + v.w * v.w;
        }
        sy2[j] = acc * LOG2E;
    }
    for (int k = t; k < (NWARP - 1) * MCOLS; k += TPB)
        ((u64*)ring)[k] = 0ull;                    // tag 0 = not ready

    // ---- x rows (2 per thread) packed f32x2 once ----
    u64 ax0[16], ax1[16];
    float xx0 = 0.f, xx1 = 0.f;
    {
        const float4* r0 = (const float4*)(xb + (size_t)(2 * t)     * DDIM);
        const float4* r1 = (const float4*)(xb + (size_t)(2 * t + 1) * DDIM);
        #pragma unroll
        for (int c = 0; c < 8; c++) {
            float4 v0 = r0[c], v1r = r1[c];
            PACK_F32X2(ax0[2*c],   v0.x,  v0.y);
            PACK_F32X2(ax0[2*c+1], v0.z,  v0.w);
            PACK_F32X2(ax1[2*c],   v1r.x, v1r.y);
            PACK_F32X2(ax1[2*c+1], v1r.z, v1r.w);
            xx0 += v0.x*v0.x + v0.y*v0.y + v0.z*v0.z + v0.w*v0.w;
            xx1 += v1r.x*v1r.x + v1r.y*v1r.y + v1r.z*v1r.z + v1r.w*v1r.w;
        }
    }
    xx0 *= LOG2E; xx1 *= LOG2E;
    __syncthreads();   // staging + ring init complete

    // ---- DP state (scaled domain) ----
    float left0 = BIGF, left1 = BIGF;
    float tl = (t == 0) ? 0.f : BIGF;

    volatile u64* myring = (w < NWARP - 1) ? &ring[w][0]     : 0;
    volatile u64* upring = (w > 0)         ? &ring[w - 1][0] : 0;

    // ---- startup cushion: wait until producer warp is SLACK columns ahead ----
    if (w > 0) {
        u64 wd;
        do { wd = upring[SLACK]; } while ((unsigned)(wd >> 32) != (unsigned)(SLACK + 1));
    }

    // ---- warp-local self-timed pipeline, branch-free body ----
    #pragma unroll 4
    for (int i = 0; i < ITERS; i++) {
        float up_sh = __shfl_up_sync(0xffffffffu, left1, 1);
        const int jj  = i - lane;
        const int jjc = jj & 255;                 // clamped smem index
        const int ii  = (i < MCOLS) ? i : (MCOLS - 1);

        u64 word = 0ull;
        if (w > 0) word = upring[ii];             // optimistic early read (broadcast)

        // ---- distances (independent stream, overlaps ring read + prev chain) ----
        u64 a0 = 0ull, b0 = 0ull, a1 = 0ull, b1 = 0ull;
        #pragma unroll
        for (int c = 0; c < 8; c++) {
            ulonglong2 yv = sy4[c * 257 + jjc];   // LDS.128 -> two f32x2
            FMA_F32X2(a0, ax0[2*c],   yv.x);
            FMA_F32X2(b0, ax0[2*c+1], yv.y);
            FMA_F32X2(a1, ax1[2*c],   yv.x);
            FMA_F32X2(b1, ax1[2*c+1], yv.y);
        }
        float l0,h0,l0b,h0b,l1,h1,l1b,h1b;
        UNPACK_F32X2(l0,  h0,  a0);
        UNPACK_F32X2(l0b, h0b, b0);
        UNPACK_F32X2(l1,  h1,  a1);
        UNPACK_F32X2(l1b, h1b, b1);
        float dot0 = (l0 + h0) + (l0b + h0b);
        float dot1 = (l1 + h1) + (l1b + h1b);
        float syy  = sy2[jjc];
        float dist0 = fmaxf(fmaf(dot0, -2.f * LOG2E, xx0 + syy), 0.f);
        float dist1 = fmaxf(fmaf(dot1, -2.f * LOG2E, xx1 + syy), 0.f);

        // ---- tag check (rarely spins; uniform branch) ----
        if (w > 0 && i < MCOLS) {
            while ((unsigned)(word >> 32) != (unsigned)(ii + 1))
                word = upring[ii];
        }
        float up0 = (lane == 0)
                  ? ((w == 0) ? BIGF : __uint_as_float((unsigned)word))
                  : up_sh;

        // ---- 2-cell softmin chain ----
        float v0  = dist0 + softmin3s(up0, left0, tl);
        float nv1 = dist1 + softmin3s(v0,  left1, left0);

        // ---- predicated commit ----
        const bool act = (jj >= 0) && (jj < MCOLS);
        if (act) {
            tl = up0; left0 = v0; left1 = nv1;
            if (lane == 31 && w < NWARP - 1)
                myring[jj] = ((u64)(unsigned)(jj + 1) << 32) | (u64)__float_as_uint(nv1);
            if (w == NWARP - 1 && lane == 31 && jj == MCOLS - 1)
                g_part[b] = nv1;                  // scaled D[N][M]
        }
    }

    // ---- fused grid reduction (last CTA) ----
    __threadfence();
    __syncthreads();
    if (t == 0) islast = (atomicAdd(&g_count, 1) == BATCH - 1);
    __syncthreads();
    if (islast) {
        __threadfence();
        red[t] = g_part[t] + g_part[t + TPB];
        __syncthreads();
        #pragma unroll
        for (int off = TPB / 2; off > 0; off >>= 1) {
            if (t < off) red[t] += red[t + off];
            __syncthreads();
        }
        if (t == 0) {
            out[0] = red[0] * (1.0f / ((float)BATCH * LOG2E));
            g_count = 0;                          // reset for next graph replay
        }
    }
}

extern "C" void kernel_launch(void* const* d_in, const int* in_sizes, int n_in,
                              void* d_out, int out_size) {
    const float* x = (const float*)d_in[0];
    const float* y = (const float*)d_in[1];
    float* out = (float*)d_out;
    sdtw_kernel<<<BATCH, TPB>>>(x, y, out);
}